// round 7
// baseline (speedup 1.0000x reference)
#include <cuda_runtime.h>
#include <cuda_bf16.h>
#include <cstdint>

// Problem constants
#define BS        8
#define RDIM      256
#define NBLK      (BS * RDIM)      // 2048
#define NODES     64
#define MROWS     (NBLK * NODES)   // 131072
#define ENC       31
#define FIN       32
#define HEADS     8
#define HID       64
#define OUTC      32
#define HC12      (HEADS * HID)    // 512
#define HC3       (HEADS * OUTC)   // 256
#define NEG_SLOPE 0.2f

typedef unsigned long long ull;
typedef __nv_bfloat16 bf16;

// ---------------- packed fp32x2 helpers ----------------
__device__ __forceinline__ ull pack2(float x, float y) {
    ull r; asm("mov.b64 %0, {%1, %2};" : "=l"(r) : "f"(x), "f"(y)); return r;
}
__device__ __forceinline__ ull fma2(ull a, ull b, ull c) {
    ull d; asm("fma.rn.f32x2 %0, %1, %2, %3;" : "=l"(d) : "l"(a), "l"(b), "l"(c)); return d;
}
__device__ __forceinline__ float2 unpack2(ull v) {
    float2 f; asm("mov.b64 {%0, %1}, %2;" : "=f"(f.x), "=f"(f.y) : "l"(v)); return f;
}
__device__ __forceinline__ uint32_t smem_u32(const void* p) {
    uint32_t a;
    asm("{ .reg .u64 t; cvta.to.shared.u64 t, %1; cvt.u32.u64 %0, t; }" : "=r"(a) : "l"(p));
    return a;
}

// ---------------- mma.sync / ldmatrix / cp.async ----------------
__device__ __forceinline__ void ldsm4(uint32_t* r, uint32_t addr) {
    asm volatile("ldmatrix.sync.aligned.m8n8.x4.shared.b16 {%0,%1,%2,%3}, [%4];"
        : "=r"(r[0]), "=r"(r[1]), "=r"(r[2]), "=r"(r[3]) : "r"(addr));
}
__device__ __forceinline__ void mma16816(float* d, const uint32_t* a, const uint32_t* b) {
    asm volatile(
        "mma.sync.aligned.m16n8k16.row.col.f32.bf16.bf16.f32 "
        "{%0,%1,%2,%3}, {%4,%5,%6,%7}, {%8,%9}, {%0,%1,%2,%3};"
        : "+f"(d[0]), "+f"(d[1]), "+f"(d[2]), "+f"(d[3])
        : "r"(a[0]), "r"(a[1]), "r"(a[2]), "r"(a[3]), "r"(b[0]), "r"(b[1]));
}
__device__ __forceinline__ void cp16(uint32_t dst, const void* src) {
    asm volatile("cp.async.cg.shared.global [%0], [%1], 16;" :: "r"(dst), "l"(src));
}
#define CP_COMMIT() asm volatile("cp.async.commit_group;" ::: "memory")
#define CP_WAIT(n)  asm volatile("cp.async.wait_group %0;" :: "n"(n) : "memory")

// ---------------- device scratch ----------------
__device__ bf16 g_a0h[(size_t)MROWS * 64],  g_a0l[(size_t)MROWS * 64];
__device__ bf16 g_a1h[(size_t)MROWS * HC12], g_a1l[(size_t)MROWS * HC12];
__device__ bf16 g_a2h[(size_t)MROWS * HC12], g_a2l[(size_t)MROWS * HC12];
__device__ bf16 g_w1h[512 * 64],  g_w1l[512 * 64];
__device__ bf16 g_w2h[512 * 512], g_w2l[512 * 512];
__device__ bf16 g_w3h[256 * 512], g_w3l[256 * 512];

// ---------------- prep kernels ----------------
__global__ void build_x0_split(const float* __restrict__ xs,
                               const float* __restrict__ pos_enc,
                               bf16* __restrict__ ah, bf16* __restrict__ al) {
    int idx = blockIdx.x * blockDim.x + threadIdx.x;   // MROWS*64
    if (idx >= MROWS * 64) return;
    int m = idx >> 6;
    int f = idx & 63;
    float v = 0.f;
    if (f == 0) v = xs[m];
    else if (f < FIN) {
        int b = m / (RDIM * NODES);
        int n = m % NODES;
        v = pos_enc[(b * NODES + n) * ENC + (f - 1)];
    }
    bf16 h = __float2bfloat16(v);
    ah[idx] = h;
    al[idx] = __float2bfloat16(v - __bfloat162float(h));
}

// W [Ksrc, N] -> Wt_hi/lo [N, Kpad] (transposed, zero-padded, split)
__global__ void prep_w(const float* __restrict__ W, bf16* __restrict__ th,
                       bf16* __restrict__ tl, int Ksrc, int N, int Kpad) {
    int idx = blockIdx.x * blockDim.x + threadIdx.x;
    if (idx >= N * Kpad) return;
    int n = idx / Kpad, k = idx % Kpad;
    float v = (k < Ksrc) ? W[(size_t)k * N + n] : 0.f;
    bf16 h = __float2bfloat16(v);
    th[idx] = h;
    tl[idx] = __float2bfloat16(v - __bfloat162float(h));
}

// ---------------- fused GEMM (split-bf16 x3 HMMA) + GAT attention ----------------
// Tile 128x64. 2-stage cp.async pipeline (single sync/iter); sC aliases stages.
// MMA ordering is TERM-MAJOR: 8 independent accumulators between same-acc reuse.
#define STAGE 24576
#define STS_OFF(row, c) ((row) * 64 + ((((c) ^ (((row) >> 1) & 3))) << 4))

template<int K, int CH, int OMODE>
__global__ __launch_bounds__(256) void gemm_attn(
    const bf16* __restrict__ Ah, const bf16* __restrict__ Al,
    const bf16* __restrict__ Bh, const bf16* __restrict__ Bl,
    const float* __restrict__ a_src, const float* __restrict__ a_dst,
    const float* __restrict__ bias,
    bf16* __restrict__ oh, bf16* __restrict__ ol,
    float* __restrict__ outmean) {
    constexpr int HPT = 64 / CH;     // heads per tile
    constexpr int U   = 2 * HPT;     // attention units per CTA
    constexpr int TU  = 256 / U;     // threads per unit
    constexpr int T   = K / 32;

    extern __shared__ __align__(16) char smem[];
    float* sC  = (float*)smem;                        // [128][68] (alias)
    float* sP  = (float*)(smem + 49152);              // [U][64][65]
    float* sLS = (float*)(smem + 49152 + U * 64 * 65 * 4);
    float* sLD = sLS + U * 64;
    float* sAS = sLD + U * 64;
    float* sAD = sAS + 64;
    float* sBI = sAD + 64;

    const int tid  = threadIdx.x;
    const int wid  = tid >> 5;
    const int lane = tid & 31;
    const int row0 = blockIdx.y * 128;
    const int col0 = blockIdx.x * 64;
    const uint32_t smem_base = smem_u32(smem);

    // ---- GEMM global->smem mapping (16B chunks) ----
    const int arow0 = tid >> 2;
    const int ac    = tid & 3;
    const uint32_t a_sts0 = STS_OFF(arow0, ac);
    const uint32_t a_sts1 = STS_OFF(arow0 + 64, ac);
    const uint32_t b_sts  = STS_OFF(arow0, ac);

    const bf16* gAh0 = Ah + (size_t)(row0 + arow0) * K + ac * 8;
    const bf16* gAh1 = gAh0 + (size_t)64 * K;
    const bf16* gAl0 = Al + (size_t)(row0 + arow0) * K + ac * 8;
    const bf16* gAl1 = gAl0 + (size_t)64 * K;
    const bf16* gBh  = Bh + (size_t)(col0 + arow0) * K + ac * 8;
    const bf16* gBl  = Bl + (size_t)(col0 + arow0) * K + ac * 8;

    const int mr = (wid & 3) * 32;
    const int nb = (wid >> 2) * 32;
    const int rowlA = (lane & 7) + ((lane >> 3) & 1) * 8;
    const int chA   = (lane >> 4);
    const int rowlB = (lane & 7) + (lane >> 4) * 8;
    const int chB   = (lane >> 3) & 1;

    float acc[2][4][4];
    #pragma unroll
    for (int i = 0; i < 2; i++)
        #pragma unroll
        for (int j = 0; j < 4; j++)
            #pragma unroll
            for (int q = 0; q < 4; q++) acc[i][j][q] = 0.f;

    auto issue_stage = [&](int s, int k0) {
        const uint32_t sb = smem_base + s * STAGE;
        cp16(sb + a_sts0, gAh0 + k0);
        cp16(sb + a_sts1, gAh1 + k0);
        cp16(sb + 8192 + a_sts0, gAl0 + k0);
        cp16(sb + 8192 + a_sts1, gAl1 + k0);
        cp16(sb + 16384 + b_sts, gBh + k0);
        cp16(sb + 20480 + b_sts, gBl + k0);
    };

    issue_stage(0, 0);
    CP_COMMIT();

    #pragma unroll 1
    for (int t = 0; t < T; t++) {
        CP_WAIT(0);                   // stage t landed (only group outstanding)
        __syncthreads();              // visible to all; prior reads of buf done
        if (t + 1 < T) {
            issue_stage((t + 1) & 1, (t + 1) * 32);   // overlaps compute below
            CP_COMMIT();
        }

        const uint32_t stg = smem_base + (t & 1) * STAGE;
        #pragma unroll
        for (int kk = 0; kk < 2; kk++) {
            const int c0 = kk * 2;
            uint32_t fAh[2][4], fAl[2][4], fBh[2][4], fBl[2][4];
            #pragma unroll
            for (int sm = 0; sm < 2; sm++) {
                int r = mr + sm * 16 + rowlA;
                uint32_t off = r * 64 + (((c0 + chA) ^ ((r >> 1) & 3)) << 4);
                ldsm4(fAh[sm], stg + off);
                ldsm4(fAl[sm], stg + 8192 + off);
            }
            #pragma unroll
            for (int tp = 0; tp < 2; tp++) {
                int r = nb + tp * 16 + rowlB;
                uint32_t off = r * 64 + (((c0 + chB) ^ ((r >> 1) & 3)) << 4);
                ldsm4(fBh[tp], stg + 16384 + off);
                ldsm4(fBl[tp], stg + 20480 + off);
            }
            // term-major: 8 independent accumulators between same-acc reuse
            #pragma unroll
            for (int sm = 0; sm < 2; sm++)
                #pragma unroll
                for (int tn = 0; tn < 4; tn++) {
                    const int tp = tn >> 1, hf = (tn & 1) * 2;
                    const uint32_t bh[2] = {fBh[tp][hf], fBh[tp][hf + 1]};
                    mma16816(acc[sm][tn], fAh[sm], bh);
                }
            #pragma unroll
            for (int sm = 0; sm < 2; sm++)
                #pragma unroll
                for (int tn = 0; tn < 4; tn++) {
                    const int tp = tn >> 1, hf = (tn & 1) * 2;
                    const uint32_t bl[2] = {fBl[tp][hf], fBl[tp][hf + 1]};
                    mma16816(acc[sm][tn], fAh[sm], bl);
                }
            #pragma unroll
            for (int sm = 0; sm < 2; sm++)
                #pragma unroll
                for (int tn = 0; tn < 4; tn++) {
                    const int tp = tn >> 1, hf = (tn & 1) * 2;
                    const uint32_t bh[2] = {fBh[tp][hf], fBh[tp][hf + 1]};
                    mma16816(acc[sm][tn], fAl[sm], bh);
                }
        }
    }
    __syncthreads();                  // all ldsm reads done; safe to alias sC

    // ---- epilogue: fragments -> sC [128][68] ----
    {
        const int gid = lane >> 2;
        const int tig = lane & 3;
        #pragma unroll
        for (int sm = 0; sm < 2; sm++) {
            #pragma unroll
            for (int tn = 0; tn < 4; tn++) {
                int r = mr + sm * 16 + gid;
                int c = nb + tn * 8 + tig * 2;
                *(float2*)&sC[r * 68 + c] = make_float2(acc[sm][tn][0], acc[sm][tn][1]);
                *(float2*)&sC[(r + 8) * 68 + c] = make_float2(acc[sm][tn][2], acc[sm][tn][3]);
            }
        }
    }
    if (tid < 64) {
        sAS[tid] = a_src[col0 + tid];
        sAD[tid] = a_dst[col0 + tid];
        sBI[tid] = bias[col0 + tid];
    }
    __syncthreads();

    // ---- attention phase ----
    const int u  = tid / TU;
    const int ut = tid % TU;
    const int sb = u / HPT;              // sub graph block 0/1
    const int hl = u % HPT;              // head within tile
    const int cb = hl * CH;

    if (ut < 64) {
        const int n = ut;
        const float* hp = &sC[(sb * 64 + n) * 68 + cb];
        float ls = 0.f, ld = 0.f;
        #pragma unroll
        for (int c = 0; c < CH; c++) {
            float hv = hp[c];
            ls += hv * sAS[cb + c];
            ld += hv * sAD[cb + c];
        }
        sLS[u * 64 + n] = ls;
        sLD[u * 64 + n] = ld;
    }
    __syncthreads();

    {   // softmax: warps of the unit stride rows
        constexpr int NWU = TU / 32;
        const int lw = ut >> 5;
        const float ls0 = sLS[u * 64 + lane];
        const float ls1 = sLS[u * 64 + lane + 32];
        for (int i = lw; i < 64; i += NWU) {
            const float ldi = sLD[u * 64 + i];
            float v0 = ldi + ls0;
            float v1 = ldi + ls1;
            v0 = (v0 > 0.f) ? v0 : NEG_SLOPE * v0;
            v1 = (v1 > 0.f) ? v1 : NEG_SLOPE * v1;
            float mx = fmaxf(v0, v1);
            #pragma unroll
            for (int o = 16; o > 0; o >>= 1)
                mx = fmaxf(mx, __shfl_xor_sync(0xffffffffu, mx, o));
            float e0 = __expf(v0 - mx);
            float e1 = __expf(v1 - mx);
            float s = e0 + e1;
            #pragma unroll
            for (int o = 16; o > 0; o >>= 1)
                s += __shfl_xor_sync(0xffffffffu, s, o);
            float inv = 1.f / s;
            sP[(u * 64 + i) * 65 + lane]      = e0 * inv;
            sP[(u * 64 + i) * 65 + lane + 32] = e1 * inv;
        }
    }
    __syncthreads();

    {   // AV: out[i][c] = sum_j P[i][j] h[j][c]; thread covers 32 cols of row i
        const int q    = ut >> 6;
        const int i    = ut & 63;
        const int coff = cb + q * 32;
        ull avac[16];
        #pragma unroll
        for (int t = 0; t < 16; t++) avac[t] = 0ull;

        const float* prow = &sP[(u * 64 + i) * 65];
        #pragma unroll 8
        for (int j = 0; j < 64; j++) {
            float p = prow[j];
            ull pp = pack2(p, p);
            const ulonglong2* hrow = (const ulonglong2*)&sC[(sb * 64 + j) * 68 + coff];
            #pragma unroll
            for (int t = 0; t < 8; t++) {
                ulonglong2 hv = hrow[t];
                avac[2 * t]     = fma2(pp, hv.x, avac[2 * t]);
                avac[2 * t + 1] = fma2(pp, hv.y, avac[2 * t + 1]);
            }
        }
        float ob[32];
        #pragma unroll
        for (int t = 0; t < 16; t++) {
            float2 f = unpack2(avac[t]);
            ob[2 * t] = f.x; ob[2 * t + 1] = f.y;
        }
        #pragma unroll
        for (int k = 0; k < 32; k++) ob[k] += sBI[coff + k];

        if (OMODE == 1) {
            const size_t m  = (size_t)(row0 + sb * 64 + i);
            const size_t go = m * HC12 + col0 + coff;
            uint uh[16], ulo[16];
            #pragma unroll
            for (int k = 0; k < 16; k++) {
                float v0 = ob[2 * k], v1 = ob[2 * k + 1];
                bf16 h0 = __float2bfloat16(v0);
                bf16 h1 = __float2bfloat16(v1);
                float r0 = v0 - __bfloat162float(h0);
                float r1 = v1 - __bfloat162float(h1);
                bf16 l0 = __float2bfloat16(r0);
                bf16 l1 = __float2bfloat16(r1);
                uh[k]  = (uint)__bfloat16_as_ushort(h0) | ((uint)__bfloat16_as_ushort(h1) << 16);
                ulo[k] = (uint)__bfloat16_as_ushort(l0) | ((uint)__bfloat16_as_ushort(l1) << 16);
            }
            #pragma unroll
            for (int k = 0; k < 4; k++) {
                *(uint4*)(oh + go + k * 8) = make_uint4(uh[4*k], uh[4*k+1], uh[4*k+2], uh[4*k+3]);
                *(uint4*)(ol + go + k * 8) = make_uint4(ulo[4*k], ulo[4*k+1], ulo[4*k+2], ulo[4*k+3]);
            }
        } else {
            __syncthreads();                 // P dead; reuse as sO [U][64][33]
            float* sO = sP;
            #pragma unroll
            for (int k = 0; k < 32; k++)
                sO[(u * 64 + i) * 33 + k] = ob[k];
            __syncthreads();
            if (ut < 32) {
                const int c = ut;
                float s = 0.f;
                #pragma unroll 8
                for (int n = 0; n < 64; n++)
                    s += sO[(u * 64 + n) * 33 + c];
                const int g  = blockIdx.y * 2 + sb;
                const int hd = blockIdx.x * HPT + hl;
                outmean[(size_t)g * HC3 + hd * 32 + c] = s * (1.0f / 64.f);
            }
        }
    }
}

// ---------------------------------------------------------------------
extern "C" void kernel_launch(void* const* d_in, const int* in_sizes, int n_in,
                              void* d_out, int out_size) {
    const float* xs      = (const float*)d_in[0];
    const float* pos_enc = (const float*)d_in[1];
    const float* W1  = (const float*)d_in[2];
    const float* as1 = (const float*)d_in[3];
    const float* ad1 = (const float*)d_in[4];
    const float* b1  = (const float*)d_in[5];
    const float* W2  = (const float*)d_in[6];
    const float* as2 = (const float*)d_in[7];
    const float* ad2 = (const float*)d_in[8];
    const float* b2  = (const float*)d_in[9];
    const float* W3  = (const float*)d_in[10];
    const float* as3 = (const float*)d_in[11];
    const float* ad3 = (const float*)d_in[12];
    const float* b3  = (const float*)d_in[13];
    float* out = (float*)d_out;

    bf16 *a0h, *a0l, *a1h, *a1l, *a2h, *a2l;
    bf16 *w1h, *w1l, *w2h, *w2l, *w3h, *w3l;
    cudaGetSymbolAddress((void**)&a0h, g_a0h);
    cudaGetSymbolAddress((void**)&a0l, g_a0l);
    cudaGetSymbolAddress((void**)&a1h, g_a1h);
    cudaGetSymbolAddress((void**)&a1l, g_a1l);
    cudaGetSymbolAddress((void**)&a2h, g_a2h);
    cudaGetSymbolAddress((void**)&a2l, g_a2l);
    cudaGetSymbolAddress((void**)&w1h, g_w1h);
    cudaGetSymbolAddress((void**)&w1l, g_w1l);
    cudaGetSymbolAddress((void**)&w2h, g_w2h);
    cudaGetSymbolAddress((void**)&w2l, g_w2l);
    cudaGetSymbolAddress((void**)&w3h, g_w3h);
    cudaGetSymbolAddress((void**)&w3l, g_w3l);

    // dynamic smem sizes
    const int SME64 = 49152 + 2 * 64 * 65 * 4 + 2 * (2 * 64 * 4) + 3 * 256;  // 84224
    const int SME32 = 49152 + 4 * 64 * 65 * 4 + 2 * (4 * 64 * 4) + 3 * 256;  // 118528
    cudaFuncSetAttribute(gemm_attn<64, 64, 1>,
        cudaFuncAttributeMaxDynamicSharedMemorySize, SME64);
    cudaFuncSetAttribute(gemm_attn<512, 64, 1>,
        cudaFuncAttributeMaxDynamicSharedMemorySize, SME64);
    cudaFuncSetAttribute(gemm_attn<512, 32, 0>,
        cudaFuncAttributeMaxDynamicSharedMemorySize, SME32);

    // prep
    build_x0_split<<<(MROWS * 64 + 255) / 256, 256>>>(xs, pos_enc, a0h, a0l);
    prep_w<<<(512 * 64 + 255) / 256, 256>>>(W1, w1h, w1l, FIN, HC12, 64);
    prep_w<<<(512 * 512 + 255) / 256, 256>>>(W2, w2h, w2l, HC12, HC12, 512);
    prep_w<<<(256 * 512 + 255) / 256, 256>>>(W3, w3h, w3l, HC12, HC3, 512);

    // layer 1
    gemm_attn<64, 64, 1><<<dim3(HEADS, MROWS / 128), 256, SME64>>>(
        a0h, a0l, w1h, w1l, as1, ad1, b1, a1h, a1l, nullptr);
    // layer 2
    gemm_attn<512, 64, 1><<<dim3(HEADS, MROWS / 128), 256, SME64>>>(
        a1h, a1l, w2h, w2l, as2, ad2, b2, a2h, a2l, nullptr);
    // layer 3
    gemm_attn<512, 32, 0><<<dim3(HC3 / 64, MROWS / 128), 256, SME32>>>(
        a2h, a2l, w3h, w3l, as3, ad3, b3, nullptr, nullptr, out);
}